// round 1
// baseline (speedup 1.0000x reference)
#include <cuda_runtime.h>
#include <math.h>

// Problem constants
#define BB 4
#define TT 1024
#define DD 512
#define HH 8
#define DHH 64
#define R2 2047   // 2T-1

// Scratch (allocation-free rule: __device__ globals)
__device__ float g_q[BB*TT*DD];
__device__ float g_k[BB*TT*DD];
__device__ float g_v[BB*TT*DD];
__device__ float g_pe[R2*DD];
__device__ float g_E[R2*DD];
__device__ float g_att[BB*TT*DD];

// ---------------------------------------------------------------------------
// Relative sinusoidal positional encoding slice: pe[r,d], r in [0,2047), with
// pos = 1023 - r (derived: global pe index g has pos = 2047-g; slice starts at
// g=1024). Even d: sin(pos*inv_freq), odd d: cos. inv_freq in fp32 to match
// jnp; sin/cos evaluated in double of the fp32 angle for accuracy.
// ---------------------------------------------------------------------------
__global__ void pe_kernel(float* __restrict__ pe) {
    int idx = blockIdx.x * blockDim.x + threadIdx.x;
    if (idx >= R2 * DD) return;
    int r = idx >> 9;        // /512
    int d = idx & 511;
    int m = d >> 1;
    float inv_freq = powf(10000.0f, -2.0f * (float)m / 512.0f);
    float ang = (float)(1023 - r) * inv_freq;
    double a = (double)ang;
    pe[idx] = (d & 1) ? (float)cos(a) : (float)sin(a);
}

// ---------------------------------------------------------------------------
// C[M,512] = A[M,512] @ W[512,512]^T + bias  (row-major, W row n = output col n)
// 64x64 tile, 256 threads, 4x4 microtile, K-step 16.
// ---------------------------------------------------------------------------
__global__ void gemm_nt(const float* __restrict__ A, const float* __restrict__ W,
                        const float* __restrict__ bias, float* __restrict__ C,
                        int M) {
    __shared__ float As[64][17];
    __shared__ float Ws[64][17];
    const int tid = threadIdx.x;
    const int tx = tid & 15, ty = tid >> 4;
    const int m0 = blockIdx.y * 64, n0 = blockIdx.x * 64;
    float acc[4][4] = {{0.f}};

    for (int k0 = 0; k0 < 512; k0 += 16) {
        #pragma unroll
        for (int i = tid; i < 1024; i += 256) {
            int r = i >> 4, kk = i & 15;
            As[r][kk] = (m0 + r < M) ? A[(size_t)(m0 + r) * 512 + k0 + kk] : 0.f;
            Ws[r][kk] = W[(size_t)(n0 + r) * 512 + k0 + kk];
        }
        __syncthreads();
        #pragma unroll
        for (int kk = 0; kk < 16; kk++) {
            float a[4], w[4];
            #pragma unroll
            for (int u = 0; u < 4; u++) a[u] = As[ty * 4 + u][kk];
            #pragma unroll
            for (int u = 0; u < 4; u++) w[u] = Ws[tx * 4 + u][kk];
            #pragma unroll
            for (int ii = 0; ii < 4; ii++)
                #pragma unroll
                for (int jj = 0; jj < 4; jj++)
                    acc[ii][jj] = fmaf(a[ii], w[jj], acc[ii][jj]);
        }
        __syncthreads();
    }
    #pragma unroll
    for (int ii = 0; ii < 4; ii++) {
        int m = m0 + ty * 4 + ii;
        if (m < M) {
            #pragma unroll
            for (int jj = 0; jj < 4; jj++) {
                int n = n0 + tx * 4 + jj;
                C[(size_t)m * 512 + n] = acc[ii][jj] + bias[n];
            }
        }
    }
}

// ---------------------------------------------------------------------------
// Fused relative-position flash attention.
// One block = (b, h, 64-query tile). 256 threads = 16x16, 4x4 microtiles.
//
// Per key tile j0 (64 keys):
//   S[i][j] = (Qu[i].K[j] + Qv[i].E[j-i+1023]) / 8
// The E term is computed as a regular 64x128 GEMM into smem:
//   R[i][rr] = Qv[i] . E[rbase+rr],  rbase = j0-i0+960, rr = j-i+63 in [0,126]
// then gathered diagonally. Online softmax + P@V accumulate (flash style).
//
// Dynamic smem layout (floats):
//   qs   [64][65]   @ 0       (4160)
//   ks   [64][65]   @ 4160
//   vs   [64][65]   @ 8320
//   es   [128][65]  @ 12480   (8320)  -- Ps [64][65] aliases es (safe: synced)
//   Rs   [64][132]  @ 20800   (8448)
//   ub   [64]       @ 29248
//   vb   [64]       @ 29312
// total 29376 floats = 117504 B
// ---------------------------------------------------------------------------
#define ATTN_SMEM_FLOATS 29376

__global__ void attn_kernel(const float* __restrict__ q, const float* __restrict__ k,
                            const float* __restrict__ v, const float* __restrict__ E,
                            const float* __restrict__ u_bias, const float* __restrict__ v_bias,
                            float* __restrict__ out) {
    extern __shared__ float sm[];
    float* qs = sm;
    float* ks = sm + 4160;
    float* vs = sm + 8320;
    float* es = sm + 12480;
    float* Ps = es;           // alias: es fully consumed before Ps is written
    float* Rs = sm + 20800;
    float* ub = sm + 29248;
    float* vb = sm + 29312;

    const int b = blockIdx.z, h = blockIdx.y;
    const int i0 = blockIdx.x * 64;
    const int tid = threadIdx.x;
    const int tx = tid & 15, ty = tid >> 4;
    const int hoff = h * DHH;

    // Load query tile (projection output, bias added on the fly)
    for (int i = tid; i < 4096; i += 256) {
        int r = i >> 6, d = i & 63;
        qs[r * 65 + d] = q[(size_t)(b * TT + i0 + r) * DD + hoff + d];
    }
    if (tid < 64) { ub[tid] = u_bias[hoff + tid]; vb[tid] = v_bias[hoff + tid]; }

    float m_i[4], l_i[4], O[4][4];
    #pragma unroll
    for (int ii = 0; ii < 4; ii++) {
        m_i[ii] = -INFINITY;
        l_i[ii] = 0.f;
        #pragma unroll
        for (int dd = 0; dd < 4; dd++) O[ii][dd] = 0.f;
    }
    __syncthreads();

    for (int kb = 0; kb < 16; kb++) {
        const int j0 = kb * 64;

        // Stage K, V tiles and the 127 needed E rows
        for (int i = tid; i < 4096; i += 256) {
            int r = i >> 6, d = i & 63;
            size_t g = (size_t)(b * TT + j0 + r) * DD + hoff + d;
            ks[r * 65 + d] = k[g];
            vs[r * 65 + d] = v[g];
        }
        const int rbase = j0 - i0 + 960;   // in [0, 1920]; rbase+126 <= 2046
        for (int i = tid; i < 8192; i += 256) {
            int r = i >> 6, d = i & 63;
            es[r * 65 + d] = (r < 127) ? E[(size_t)(rbase + r) * DD + hoff + d] : 0.f;
        }
        __syncthreads();

        // R = (qs + vb) @ es^T  -> Rs[64][127]
        float accR[4][8];
        #pragma unroll
        for (int ii = 0; ii < 4; ii++)
            #pragma unroll
            for (int c = 0; c < 8; c++) accR[ii][c] = 0.f;
        for (int d = 0; d < 64; d++) {
            const float vbd = vb[d];
            float qv[4], ee[8];
            #pragma unroll
            for (int ii = 0; ii < 4; ii++) qv[ii] = qs[(ty * 4 + ii) * 65 + d] + vbd;
            #pragma unroll
            for (int c = 0; c < 8; c++) ee[c] = es[(tx * 8 + c) * 65 + d];
            #pragma unroll
            for (int ii = 0; ii < 4; ii++)
                #pragma unroll
                for (int c = 0; c < 8; c++)
                    accR[ii][c] = fmaf(qv[ii], ee[c], accR[ii][c]);
        }
        #pragma unroll
        for (int ii = 0; ii < 4; ii++)
            #pragma unroll
            for (int c = 0; c < 8; c++)
                Rs[(ty * 4 + ii) * 132 + tx * 8 + c] = accR[ii][c];

        // S_K = (qs + ub) @ ks^T (register fragments)
        float accS[4][4];
        #pragma unroll
        for (int ii = 0; ii < 4; ii++)
            #pragma unroll
            for (int jj = 0; jj < 4; jj++) accS[ii][jj] = 0.f;
        for (int d = 0; d < 64; d++) {
            const float ubd = ub[d];
            float qu[4], kk4[4];
            #pragma unroll
            for (int ii = 0; ii < 4; ii++) qu[ii] = qs[(ty * 4 + ii) * 65 + d] + ubd;
            #pragma unroll
            for (int jj = 0; jj < 4; jj++) kk4[jj] = ks[(tx * 4 + jj) * 65 + d];
            #pragma unroll
            for (int ii = 0; ii < 4; ii++)
                #pragma unroll
                for (int jj = 0; jj < 4; jj++)
                    accS[ii][jj] = fmaf(qu[ii], kk4[jj], accS[ii][jj]);
        }
        __syncthreads();  // Rs visible; all es reads done -> Ps (alias) writable

        // Combine + online softmax. Row group = 16 lanes sharing ty (lane-aligned
        // half-warp -> shfl_xor up to 8 reduces within the group).
        #pragma unroll
        for (int ii = 0; ii < 4; ii++) {
            const int il = ty * 4 + ii;
            float Srow[4];
            float mloc = -INFINITY;
            #pragma unroll
            for (int jj = 0; jj < 4; jj++) {
                const int jl = tx * 4 + jj;
                float s = (accS[ii][jj] + Rs[il * 132 + (jl - il + 63)]) * 0.125f;
                Srow[jj] = s;
                mloc = fmaxf(mloc, s);
            }
            #pragma unroll
            for (int off = 8; off >= 1; off >>= 1)
                mloc = fmaxf(mloc, __shfl_xor_sync(0xffffffffu, mloc, off));
            const float mnew = fmaxf(m_i[ii], mloc);
            const float alpha = expf(m_i[ii] - mnew);   // first tile: exp(-inf)=0
            float psum = 0.f;
            float prow[4];
            #pragma unroll
            for (int jj = 0; jj < 4; jj++) {
                float p = expf(Srow[jj] - mnew);
                prow[jj] = p;
                psum += p;
            }
            #pragma unroll
            for (int off = 8; off >= 1; off >>= 1)
                psum += __shfl_xor_sync(0xffffffffu, psum, off);
            l_i[ii] = l_i[ii] * alpha + psum;
            m_i[ii] = mnew;
            #pragma unroll
            for (int dd = 0; dd < 4; dd++) O[ii][dd] *= alpha;
            #pragma unroll
            for (int jj = 0; jj < 4; jj++)
                Ps[il * 65 + tx * 4 + jj] = prow[jj];
        }
        __syncthreads();  // Ps visible

        // O += P @ V
        for (int j = 0; j < 64; j++) {
            float pv[4], vv[4];
            #pragma unroll
            for (int ii = 0; ii < 4; ii++) pv[ii] = Ps[(ty * 4 + ii) * 65 + j];
            #pragma unroll
            for (int dd = 0; dd < 4; dd++) vv[dd] = vs[j * 65 + tx * 4 + dd];
            #pragma unroll
            for (int ii = 0; ii < 4; ii++)
                #pragma unroll
                for (int dd = 0; dd < 4; dd++)
                    O[ii][dd] = fmaf(pv[ii], vv[dd], O[ii][dd]);
        }
        __syncthreads();  // done with vs/Ps before next tile overwrites
    }

    // Epilogue: normalize and write (B,T,D) head-interleaved
    #pragma unroll
    for (int ii = 0; ii < 4; ii++) {
        const int i = i0 + ty * 4 + ii;
        const float inv = 1.f / l_i[ii];
        #pragma unroll
        for (int dd = 0; dd < 4; dd++)
            out[(size_t)(b * TT + i) * DD + hoff + tx * 4 + dd] = O[ii][dd] * inv;
    }
}

// ---------------------------------------------------------------------------
// Launch: pe -> {q,k,v,E} projections -> fused attention -> output projection.
// All on default stream (sequential deps via stream order). Graph-capturable:
// kernel launches + cudaGetSymbolAddress/cudaFuncSetAttribute only.
// ---------------------------------------------------------------------------
extern "C" void kernel_launch(void* const* d_in, const int* in_sizes, int n_in,
                              void* d_out, int out_size) {
    const float* query  = (const float*)d_in[0];
    const float* key    = (const float*)d_in[1];
    const float* value  = (const float*)d_in[2];
    const float* Wq     = (const float*)d_in[3];
    const float* bq     = (const float*)d_in[4];
    const float* Wk     = (const float*)d_in[5];
    const float* bk     = (const float*)d_in[6];
    const float* Wv     = (const float*)d_in[7];
    const float* bv     = (const float*)d_in[8];
    const float* Wp     = (const float*)d_in[9];
    const float* bp     = (const float*)d_in[10];
    const float* Wo     = (const float*)d_in[11];
    const float* bo     = (const float*)d_in[12];
    const float* u_bias = (const float*)d_in[13];
    const float* v_bias = (const float*)d_in[14];
    float* out = (float*)d_out;

    float *pq, *pk, *pv, *ppe, *pE, *patt;
    cudaGetSymbolAddress((void**)&pq,  g_q);
    cudaGetSymbolAddress((void**)&pk,  g_k);
    cudaGetSymbolAddress((void**)&pv,  g_v);
    cudaGetSymbolAddress((void**)&ppe, g_pe);
    cudaGetSymbolAddress((void**)&pE,  g_E);
    cudaGetSymbolAddress((void**)&patt, g_att);

    // 1) positional encodings
    pe_kernel<<<(R2 * DD + 255) / 256, 256>>>(ppe);

    // 2) input projections (M = B*T = 4096) and E projection (M = 2047)
    gemm_nt<<<dim3(8, 64), 256>>>(query, Wq, bq, pq, 4096);
    gemm_nt<<<dim3(8, 64), 256>>>(key,   Wk, bk, pk, 4096);
    gemm_nt<<<dim3(8, 64), 256>>>(value, Wv, bv, pv, 4096);
    gemm_nt<<<dim3(8, 32), 256>>>(ppe,   Wp, bp, pE, 2047);

    // 3) fused rel-pos flash attention
    cudaFuncSetAttribute(attn_kernel, cudaFuncAttributeMaxDynamicSharedMemorySize,
                         ATTN_SMEM_FLOATS * (int)sizeof(float));
    attn_kernel<<<dim3(16, 8, 4), 256, ATTN_SMEM_FLOATS * sizeof(float)>>>(
        pq, pk, pv, pE, u_bias, v_bias, patt);

    // 4) output projection -> d_out
    gemm_nt<<<dim3(8, 64), 256>>>(patt, Wo, bo, out, 4096);
}

// round 12
// speedup vs baseline: 2.1887x; 2.1887x over previous
#include <cuda_runtime.h>
#include <math.h>

// Problem constants
#define BB 4
#define TT 1024
#define DD 512
#define HH 8
#define DHH 64
#define R2 2047   // 2T-1

// Scratch (allocation-free rule: __device__ globals)
__device__ float g_q[BB*TT*DD];
__device__ float g_k[BB*TT*DD];
__device__ float g_v[BB*TT*DD];
__device__ float g_pe[R2*DD];
__device__ float g_E[R2*DD];
__device__ float g_att[BB*TT*DD];

// ---------------------------------------------------------------------------
// Relative sinusoidal PE slice: pe[r,d], pos = 1023 - r.
// ---------------------------------------------------------------------------
__global__ void pe_kernel(float* __restrict__ pe) {
    int idx = blockIdx.x * blockDim.x + threadIdx.x;
    if (idx >= R2 * DD) return;
    int r = idx >> 9;
    int d = idx & 511;
    int m = d >> 1;
    float inv_freq = powf(10000.0f, -2.0f * (float)m / 512.0f);
    float ang = (float)(1023 - r) * inv_freq;
    pe[idx] = (d & 1) ? cosf(ang) : sinf(ang);
}

// ---------------------------------------------------------------------------
// GEMM body: C[M,512] = A[M,512] @ W[512,512]^T + bias
// Tile 128(M) x 64(N), 256 threads, 8x4 microtile, K-step 16.
// k-major smem (transposed at staging) so fragments are single LDS.128.
// ---------------------------------------------------------------------------
__device__ __forceinline__ void gemm_body(const float* __restrict__ A,
                                          const float* __restrict__ W,
                                          const float* __restrict__ bias,
                                          float* __restrict__ C, int M,
                                          int m0, int n0) {
    __shared__ __align__(16) float AsT[16][132];
    __shared__ __align__(16) float WsT[16][68];
    const int t = threadIdx.x;
    const int tx = t & 15, ty = t >> 4;
    float acc[8][4] = {};

    for (int k0 = 0; k0 < 512; k0 += 16) {
        // Stage A (128x16) transposed
        #pragma unroll
        for (int p = 0; p < 2; p++) {
            int f = t + p * 256;
            int m = f >> 2, q4 = f & 3;
            float4 val = make_float4(0.f, 0.f, 0.f, 0.f);
            if (m0 + m < M)
                val = *(const float4*)(A + (size_t)(m0 + m) * 512 + k0 + q4 * 4);
            AsT[q4 * 4 + 0][m] = val.x;
            AsT[q4 * 4 + 1][m] = val.y;
            AsT[q4 * 4 + 2][m] = val.z;
            AsT[q4 * 4 + 3][m] = val.w;
        }
        // Stage W (64x16) transposed
        {
            int n = t >> 2, q4 = t & 3;
            float4 val = *(const float4*)(W + (size_t)(n0 + n) * 512 + k0 + q4 * 4);
            WsT[q4 * 4 + 0][n] = val.x;
            WsT[q4 * 4 + 1][n] = val.y;
            WsT[q4 * 4 + 2][n] = val.z;
            WsT[q4 * 4 + 3][n] = val.w;
        }
        __syncthreads();
        #pragma unroll
        for (int kk = 0; kk < 16; kk++) {
            float4 a0 = *(const float4*)&AsT[kk][ty * 8];
            float4 a1 = *(const float4*)&AsT[kk][ty * 8 + 4];
            float4 w4 = *(const float4*)&WsT[kk][tx * 4];
            float a[8] = {a0.x, a0.y, a0.z, a0.w, a1.x, a1.y, a1.z, a1.w};
            float w[4] = {w4.x, w4.y, w4.z, w4.w};
            #pragma unroll
            for (int u = 0; u < 8; u++)
                #pragma unroll
                for (int j = 0; j < 4; j++)
                    acc[u][j] = fmaf(a[u], w[j], acc[u][j]);
        }
        __syncthreads();
    }

    float4 b4 = *(const float4*)(bias + n0 + tx * 4);
    #pragma unroll
    for (int u = 0; u < 8; u++) {
        int m = m0 + ty * 8 + u;
        if (m < M) {
            float4 o;
            o.x = acc[u][0] + b4.x;
            o.y = acc[u][1] + b4.y;
            o.z = acc[u][2] + b4.z;
            o.w = acc[u][3] + b4.w;
            *(float4*)(C + (size_t)m * 512 + n0 + tx * 4) = o;
        }
    }
}

__global__ __launch_bounds__(256, 3) void gemm_nt(const float* __restrict__ A,
                                                  const float* __restrict__ W,
                                                  const float* __restrict__ bias,
                                                  float* __restrict__ C, int M) {
    gemm_body(A, W, bias, C, M, blockIdx.y * 128, blockIdx.x * 64);
}

// Fused QKV: z selects which projection.
__global__ __launch_bounds__(256, 3) void qkv_gemm(
    const float* __restrict__ q, const float* __restrict__ k, const float* __restrict__ v,
    const float* __restrict__ Wq, const float* __restrict__ Wk, const float* __restrict__ Wv,
    const float* __restrict__ bq, const float* __restrict__ bk, const float* __restrict__ bv,
    float* __restrict__ oq, float* __restrict__ ok, float* __restrict__ ov) {
    const float *A, *W, *bias;
    float* C;
    if (blockIdx.z == 0)      { A = q; W = Wq; bias = bq; C = oq; }
    else if (blockIdx.z == 1) { A = k; W = Wk; bias = bk; C = ok; }
    else                      { A = v; W = Wv; bias = bv; C = ov; }
    gemm_body(A, W, bias, C, 4096, blockIdx.y * 128, blockIdx.x * 64);
}

// ---------------------------------------------------------------------------
// Fused rel-pos flash attention, one block = (b, h, 64-query tile).
// score(i,j) = (q_i.k_j + cK[j] + q_i.E_r + cE[r]) / 8,  r = j - i + 1023
//   cK[j] = u_bias . k_j    cE[r] = v_bias . E_r   (rank-1 bias factoring)
// q.E computed into a 128-slot ring Rs (slot = r & 127): 64 new columns per
// key tile (63-column overlap between consecutive windows is reused).
//
// Smem layout (floats): all fragment bases 16B-aligned, stride 68 for LDS.128.
//   qT  [64][68] @ 0       k-major raw q
//   ksT [64][68] @ 4352    k-major k tile
//   esT [64][68] @ 8704    k-major E rows (64 new)  -- Ps[64][65] aliases
//   vs  [64][64] @ 13056   row-major v tile
//   Rs  [64][128]@ 17152   q.E + cE ring
//   cK  [64]     @ 25344
//   ub  [64]     @ 25408
//   vb  [64]     @ 25472
// total 25536 floats = 102144 B  -> 2 CTAs/SM
// ---------------------------------------------------------------------------
#define ATT_SMEM_FLOATS 25536

__global__ __launch_bounds__(256, 2) void attn_kernel(
    const float* __restrict__ q, const float* __restrict__ k,
    const float* __restrict__ v, const float* __restrict__ E,
    const float* __restrict__ u_bias, const float* __restrict__ v_bias,
    float* __restrict__ out) {
    extern __shared__ float sm[];
    float* qT  = sm;            // [64][68]
    float* ksT = sm + 4352;     // [64][68]
    float* esT = sm + 8704;     // [64][68]
    float* Ps  = esT;           // [64][65] alias (lifetimes disjoint via syncs)
    float* vs  = sm + 13056;    // [64][64]
    float* Rs  = sm + 17152;    // [64][128]
    float* cK  = sm + 25344;    // [64]
    float* ub  = sm + 25408;
    float* vb  = sm + 25472;

    const int b = blockIdx.z, h = blockIdx.y;
    const int i0 = blockIdx.x * 64;
    const int t = threadIdx.x;
    const int tx = t & 15, ty = t >> 4;
    const int hoff = h * DHH;

    const float* qbase = q + (size_t)(b * TT + i0) * DD + hoff;
    const float* kbase = k + (size_t)b * TT * DD + hoff;
    const float* vbase = v + (size_t)b * TT * DD + hoff;
    const float* Ebase = E + hoff;

    // ---- prologue: stage qT (transposed), biases, first 63 E columns ----
    #pragma unroll
    for (int p = 0; p < 4; p++) {
        int g = p * 256 + t;
        int r = g >> 4, dq = g & 15;
        float4 val = *(const float4*)(qbase + (size_t)r * 512 + dq * 4);
        qT[(dq * 4 + 0) * 68 + r] = val.x;
        qT[(dq * 4 + 1) * 68 + r] = val.y;
        qT[(dq * 4 + 2) * 68 + r] = val.z;
        qT[(dq * 4 + 3) * 68 + r] = val.w;
    }
    if (t < 64) { ub[t] = u_bias[hoff + t]; vb[t] = v_bias[hoff + t]; }

    const int rbase0 = 960 - i0;   // first window start (>= 0)
    // stage E rows rbase0..rbase0+62 into esT cols 0..62 (col 63 zero)
    #pragma unroll
    for (int p = 0; p < 4; p++) {
        int g = p * 256 + t;
        int c = g >> 4, dq = g & 15;
        float4 val = make_float4(0.f, 0.f, 0.f, 0.f);
        if (c < 63) val = *(const float4*)(Ebase + (size_t)(rbase0 + c) * 512 + dq * 4);
        esT[(dq * 4 + 0) * 68 + c] = val.x;
        esT[(dq * 4 + 1) * 68 + c] = val.y;
        esT[(dq * 4 + 2) * 68 + c] = val.z;
        esT[(dq * 4 + 3) * 68 + c] = val.w;
    }
    __syncthreads();

    // prologue: Rs for cols 0..62 (col 63 dummy; overwritten at kb=0)
    {
        float accR[4][4] = {};
        #pragma unroll 4
        for (int d = 0; d < 64; d++) {
            float4 a4 = *(const float4*)&qT[d * 68 + ty * 4];
            float4 e4 = *(const float4*)&esT[d * 68 + tx * 4];
            float a[4] = {a4.x, a4.y, a4.z, a4.w};
            float e[4] = {e4.x, e4.y, e4.z, e4.w};
            #pragma unroll
            for (int ii = 0; ii < 4; ii++)
                #pragma unroll
                for (int jj = 0; jj < 4; jj++)
                    accR[ii][jj] = fmaf(a[ii], e[jj], accR[ii][jj]);
        }
        // cE for these columns (from esT; col63 is zero -> cE=0)
        float cEr[4];
        #pragma unroll
        for (int jj = 0; jj < 4; jj++) {
            int c = tx * 4 + jj;
            float s = 0.f;
            for (int d = 0; d < 64; d++) s = fmaf(vb[d], esT[d * 68 + c], s);
            cEr[jj] = s;
        }
        int slot[4];
        #pragma unroll
        for (int jj = 0; jj < 4; jj++) slot[jj] = (rbase0 + tx * 4 + jj) & 127;
        #pragma unroll
        for (int ii = 0; ii < 4; ii++)
            #pragma unroll
            for (int jj = 0; jj < 4; jj++)
                Rs[(ty * 4 + ii) * 128 + slot[jj]] = accR[ii][jj] + cEr[jj];
    }

    float m_i[4], l_i[4], O[4][4];
    #pragma unroll
    for (int ii = 0; ii < 4; ii++) {
        m_i[ii] = -1e30f;
        l_i[ii] = 0.f;
        #pragma unroll
        for (int dd = 0; dd < 4; dd++) O[ii][dd] = 0.f;
    }

    // ---- main loop over key tiles ----
    for (int kb = 0; kb < 16; kb++) {
        const int j0 = kb * 64;
        const int rnb = j0 - i0 + 1023;   // base of the 64 NEW r columns

        __syncthreads();  // prev-iter consumers of ks/vs/es/Ps done

        // stage ksT (transposed), vs (row-major), esT (64 new E rows)
        #pragma unroll
        for (int p = 0; p < 4; p++) {
            int g = p * 256 + t;
            int r = g >> 4, dq = g & 15;
            float4 kv4 = *(const float4*)(kbase + (size_t)(j0 + r) * 512 + dq * 4);
            ksT[(dq * 4 + 0) * 68 + r] = kv4.x;
            ksT[(dq * 4 + 1) * 68 + r] = kv4.y;
            ksT[(dq * 4 + 2) * 68 + r] = kv4.z;
            ksT[(dq * 4 + 3) * 68 + r] = kv4.w;
            float4 vv4 = *(const float4*)(vbase + (size_t)(j0 + r) * 512 + dq * 4);
            *(float4*)(vs + r * 64 + dq * 4) = vv4;
            float4 ee4 = *(const float4*)(Ebase + (size_t)(rnb + r) * 512 + dq * 4);
            esT[(dq * 4 + 0) * 68 + r] = ee4.x;
            esT[(dq * 4 + 1) * 68 + r] = ee4.y;
            esT[(dq * 4 + 2) * 68 + r] = ee4.z;
            esT[(dq * 4 + 3) * 68 + r] = ee4.w;
        }
        // cK from global (independent of staging; L1 hits the staged lines)
        if (t < 64) {
            const float* krow = kbase + (size_t)(j0 + t) * 512;
            float s = 0.f;
            #pragma unroll 4
            for (int dq = 0; dq < 16; dq++) {
                float4 kk4 = *(const float4*)(krow + dq * 4);
                s = fmaf(ub[dq * 4 + 0], kk4.x, s);
                s = fmaf(ub[dq * 4 + 1], kk4.y, s);
                s = fmaf(ub[dq * 4 + 2], kk4.z, s);
                s = fmaf(ub[dq * 4 + 3], kk4.w, s);
            }
            cK[t] = s;
        }
        __syncthreads();  // staging + cK visible

        // fused R+S GEMM: 3x LDS.128 + 32 FFMA per d
        float accS[4][4] = {}, accR[4][4] = {};
        #pragma unroll 4
        for (int d = 0; d < 64; d++) {
            float4 a4 = *(const float4*)&qT[d * 68 + ty * 4];
            float4 k4 = *(const float4*)&ksT[d * 68 + tx * 4];
            float4 e4 = *(const float4*)&esT[d * 68 + tx * 4];
            float a[4] = {a4.x, a4.y, a4.z, a4.w};
            float kf[4] = {k4.x, k4.y, k4.z, k4.w};
            float ef[4] = {e4.x, e4.y, e4.z, e4.w};
            #pragma unroll
            for (int ii = 0; ii < 4; ii++) {
                #pragma unroll
                for (int jj = 0; jj < 4; jj++) {
                    accS[ii][jj] = fmaf(a[ii], kf[jj], accS[ii][jj]);
                    accR[ii][jj] = fmaf(a[ii], ef[jj], accR[ii][jj]);
                }
            }
        }
        // cE for the 64 new columns + ring store
        {
            float cEr[4];
            #pragma unroll
            for (int jj = 0; jj < 4; jj++) {
                int c = tx * 4 + jj;
                float s = 0.f;
                for (int d = 0; d < 64; d++) s = fmaf(vb[d], esT[d * 68 + c], s);
                cEr[jj] = s;
            }
            int slot[4];
            #pragma unroll
            for (int jj = 0; jj < 4; jj++) slot[jj] = (rnb + tx * 4 + jj) & 127;
            #pragma unroll
            for (int ii = 0; ii < 4; ii++)
                #pragma unroll
                for (int jj = 0; jj < 4; jj++)
                    Rs[(ty * 4 + ii) * 128 + slot[jj]] = accR[ii][jj] + cEr[jj];
        }
        __syncthreads();  // Rs visible; esT reads done (Ps alias writable)

        // softmax (online) — row group = 16 lanes sharing ty
        float cK4v[4];
        {
            float4 c4 = *(const float4*)&cK[tx * 4];
            cK4v[0] = c4.x; cK4v[1] = c4.y; cK4v[2] = c4.z; cK4v[3] = c4.w;
        }
        #pragma unroll
        for (int ii = 0; ii < 4; ii++) {
            const int il = ty * 4 + ii;
            float Srow[4];
            float mloc = -1e30f;
            #pragma unroll
            for (int jj = 0; jj < 4; jj++) {
                float rterm = Rs[il * 128 + ((rnb - il + tx * 4 + jj) & 127)];
                float s = (accS[ii][jj] + cK4v[jj] + rterm) * 0.125f;
                Srow[jj] = s;
                mloc = fmaxf(mloc, s);
            }
            #pragma unroll
            for (int off = 8; off >= 1; off >>= 1)
                mloc = fmaxf(mloc, __shfl_xor_sync(0xffffffffu, mloc, off));
            const float mnew = fmaxf(m_i[ii], mloc);
            const float alpha = __expf(m_i[ii] - mnew);
            float psum = 0.f;
            float prow[4];
            #pragma unroll
            for (int jj = 0; jj < 4; jj++) {
                float p = __expf(Srow[jj] - mnew);
                prow[jj] = p;
                psum += p;
            }
            #pragma unroll
            for (int off = 8; off >= 1; off >>= 1)
                psum += __shfl_xor_sync(0xffffffffu, psum, off);
            l_i[ii] = l_i[ii] * alpha + psum;
            m_i[ii] = mnew;
            #pragma unroll
            for (int dd = 0; dd < 4; dd++) O[ii][dd] *= alpha;
            #pragma unroll
            for (int jj = 0; jj < 4; jj++)
                Ps[il * 65 + tx * 4 + jj] = prow[jj];
        }
        __syncthreads();  // Ps visible

        // O += P @ V
        #pragma unroll 4
        for (int j = 0; j < 64; j++) {
            float4 v4 = *(const float4*)&vs[j * 64 + tx * 4];
            float vf[4] = {v4.x, v4.y, v4.z, v4.w};
            float pv[4];
            #pragma unroll
            for (int ii = 0; ii < 4; ii++) pv[ii] = Ps[(ty * 4 + ii) * 65 + j];
            #pragma unroll
            for (int ii = 0; ii < 4; ii++)
                #pragma unroll
                for (int dd = 0; dd < 4; dd++)
                    O[ii][dd] = fmaf(pv[ii], vf[dd], O[ii][dd]);
        }
    }

    // epilogue
    #pragma unroll
    for (int ii = 0; ii < 4; ii++) {
        const int i = i0 + ty * 4 + ii;
        const float inv = 1.f / l_i[ii];
        float4 o;
        o.x = O[ii][0] * inv;
        o.y = O[ii][1] * inv;
        o.z = O[ii][2] * inv;
        o.w = O[ii][3] * inv;
        *(float4*)(out + (size_t)(b * TT + i) * DD + hoff + tx * 4) = o;
    }
}

// ---------------------------------------------------------------------------
extern "C" void kernel_launch(void* const* d_in, const int* in_sizes, int n_in,
                              void* d_out, int out_size) {
    const float* query  = (const float*)d_in[0];
    const float* key    = (const float*)d_in[1];
    const float* value  = (const float*)d_in[2];
    const float* Wq     = (const float*)d_in[3];
    const float* bq     = (const float*)d_in[4];
    const float* Wk     = (const float*)d_in[5];
    const float* bk     = (const float*)d_in[6];
    const float* Wv     = (const float*)d_in[7];
    const float* bv     = (const float*)d_in[8];
    const float* Wp     = (const float*)d_in[9];
    const float* bp     = (const float*)d_in[10];
    const float* Wo     = (const float*)d_in[11];
    const float* bo     = (const float*)d_in[12];
    const float* u_bias = (const float*)d_in[13];
    const float* v_bias = (const float*)d_in[14];
    float* out = (float*)d_out;

    float *pq, *pk, *pv, *ppe, *pE, *patt;
    cudaGetSymbolAddress((void**)&pq,  g_q);
    cudaGetSymbolAddress((void**)&pk,  g_k);
    cudaGetSymbolAddress((void**)&pv,  g_v);
    cudaGetSymbolAddress((void**)&ppe, g_pe);
    cudaGetSymbolAddress((void**)&pE,  g_E);
    cudaGetSymbolAddress((void**)&patt, g_att);

    // 1) positional encodings
    pe_kernel<<<(R2 * DD + 255) / 256, 256>>>(ppe);

    // 2) fused QKV projections + E projection
    qkv_gemm<<<dim3(8, 32, 3), 256>>>(query, key, value, Wq, Wk, Wv,
                                      bq, bk, bv, pq, pk, pv);
    gemm_nt<<<dim3(8, 16), 256>>>(ppe, Wp, bp, pE, 2047);

    // 3) fused rel-pos flash attention
    cudaFuncSetAttribute(attn_kernel, cudaFuncAttributeMaxDynamicSharedMemorySize,
                         ATT_SMEM_FLOATS * (int)sizeof(float));
    attn_kernel<<<dim3(16, 8, 4), 256, ATT_SMEM_FLOATS * sizeof(float)>>>(
        pq, pk, pv, pE, u_bias, v_bias, patt);

    // 4) output projection -> d_out
    gemm_nt<<<dim3(8, 32), 256>>>(patt, Wo, bo, out, 4096);
}

// round 16
// speedup vs baseline: 2.5628x; 1.1709x over previous
#include <cuda_runtime.h>
#include <math.h>

// Problem constants
#define BB 4
#define TT 1024
#define DD 512
#define HH 8
#define DHH 64
#define R2 2047   // 2T-1

// Scratch (allocation-free rule: __device__ globals)
__device__ float g_q[BB*TT*DD];
__device__ float g_k[BB*TT*DD];
__device__ float g_v[BB*TT*DD];
__device__ float g_pe[R2*DD];
__device__ float g_E[R2*DD];
__device__ float g_att[BB*TT*DD];
__device__ float g_cK[BB*HH*TT];      // cK[b][h][j] = u_bias_h . k_{b,j,h}
__device__ float g_cE[HH*2048];       // cE[h][r]   = v_bias_h . E_{r,h} (stride 2048)

// ---------------------------------------------------------------------------
// Relative sinusoidal PE slice: pe[r,d], pos = 1023 - r.
// ---------------------------------------------------------------------------
__global__ void pe_kernel(float* __restrict__ pe) {
    int idx = blockIdx.x * blockDim.x + threadIdx.x;
    if (idx >= R2 * DD) return;
    int r = idx >> 9;
    int d = idx & 511;
    int m = d >> 1;
    float inv_freq = powf(10000.0f, -2.0f * (float)m / 512.0f);
    float ang = (float)(1023 - r) * inv_freq;
    pe[idx] = (d & 1) ? cosf(ang) : sinf(ang);
}

// ---------------------------------------------------------------------------
// Rank-1 bias precompute kernels (replace per-tile loops in attention).
// ---------------------------------------------------------------------------
__global__ void ck_kernel(const float* __restrict__ k, const float* __restrict__ u_bias,
                          float* __restrict__ cK) {
    int idx = blockIdx.x * blockDim.x + threadIdx.x;   // b*8192 + h*1024 + j
    if (idx >= BB * HH * TT) return;
    int j = idx & 1023;
    int h = (idx >> 10) & 7;
    int b = idx >> 13;
    const float* row = k + ((size_t)(b * TT + j)) * DD + h * DHH;
    const float* ub  = u_bias + h * DHH;
    float s = 0.f;
    #pragma unroll 4
    for (int d = 0; d < 64; d += 4) {
        float4 kv = *(const float4*)(row + d);
        float4 u4 = *(const float4*)(ub + d);
        s = fmaf(u4.x, kv.x, s);
        s = fmaf(u4.y, kv.y, s);
        s = fmaf(u4.z, kv.z, s);
        s = fmaf(u4.w, kv.w, s);
    }
    cK[idx] = s;
}

__global__ void ce_kernel(const float* __restrict__ E, const float* __restrict__ v_bias,
                          float* __restrict__ cE) {
    int idx = blockIdx.x * blockDim.x + threadIdx.x;   // h*2048 + r
    if (idx >= HH * 2048) return;
    int r = idx & 2047;
    int h = idx >> 11;
    if (r >= R2) { cE[idx] = 0.f; return; }
    const float* row = E + (size_t)r * DD + h * DHH;
    const float* vb  = v_bias + h * DHH;
    float s = 0.f;
    #pragma unroll 4
    for (int d = 0; d < 64; d += 4) {
        float4 ev = *(const float4*)(row + d);
        float4 v4 = *(const float4*)(vb + d);
        s = fmaf(v4.x, ev.x, s);
        s = fmaf(v4.y, ev.y, s);
        s = fmaf(v4.z, ev.z, s);
        s = fmaf(v4.w, ev.w, s);
    }
    cE[idx] = s;
}

// ---------------------------------------------------------------------------
// GEMM body: C[M,512] = A[M,512] @ W[512,512]^T + bias
// ---------------------------------------------------------------------------
__device__ __forceinline__ void gemm_body(const float* __restrict__ A,
                                          const float* __restrict__ W,
                                          const float* __restrict__ bias,
                                          float* __restrict__ C, int M,
                                          int m0, int n0) {
    __shared__ __align__(16) float AsT[16][132];
    __shared__ __align__(16) float WsT[16][68];
    const int t = threadIdx.x;
    const int tx = t & 15, ty = t >> 4;
    float acc[8][4] = {};

    for (int k0 = 0; k0 < 512; k0 += 16) {
        #pragma unroll
        for (int p = 0; p < 2; p++) {
            int f = t + p * 256;
            int m = f >> 2, q4 = f & 3;
            float4 val = make_float4(0.f, 0.f, 0.f, 0.f);
            if (m0 + m < M)
                val = *(const float4*)(A + (size_t)(m0 + m) * 512 + k0 + q4 * 4);
            AsT[q4 * 4 + 0][m] = val.x;
            AsT[q4 * 4 + 1][m] = val.y;
            AsT[q4 * 4 + 2][m] = val.z;
            AsT[q4 * 4 + 3][m] = val.w;
        }
        {
            int n = t >> 2, q4 = t & 3;
            float4 val = *(const float4*)(W + (size_t)(n0 + n) * 512 + k0 + q4 * 4);
            WsT[q4 * 4 + 0][n] = val.x;
            WsT[q4 * 4 + 1][n] = val.y;
            WsT[q4 * 4 + 2][n] = val.z;
            WsT[q4 * 4 + 3][n] = val.w;
        }
        __syncthreads();
        #pragma unroll
        for (int kk = 0; kk < 16; kk++) {
            float4 a0 = *(const float4*)&AsT[kk][ty * 8];
            float4 a1 = *(const float4*)&AsT[kk][ty * 8 + 4];
            float4 w4 = *(const float4*)&WsT[kk][tx * 4];
            float a[8] = {a0.x, a0.y, a0.z, a0.w, a1.x, a1.y, a1.z, a1.w};
            float w[4] = {w4.x, w4.y, w4.z, w4.w};
            #pragma unroll
            for (int u = 0; u < 8; u++)
                #pragma unroll
                for (int j = 0; j < 4; j++)
                    acc[u][j] = fmaf(a[u], w[j], acc[u][j]);
        }
        __syncthreads();
    }

    float4 b4 = *(const float4*)(bias + n0 + tx * 4);
    #pragma unroll
    for (int u = 0; u < 8; u++) {
        int m = m0 + ty * 8 + u;
        if (m < M) {
            float4 o;
            o.x = acc[u][0] + b4.x;
            o.y = acc[u][1] + b4.y;
            o.z = acc[u][2] + b4.z;
            o.w = acc[u][3] + b4.w;
            *(float4*)(C + (size_t)m * 512 + n0 + tx * 4) = o;
        }
    }
}

__global__ __launch_bounds__(256, 3) void gemm_nt(const float* __restrict__ A,
                                                  const float* __restrict__ W,
                                                  const float* __restrict__ bias,
                                                  float* __restrict__ C, int M) {
    gemm_body(A, W, bias, C, M, blockIdx.y * 128, blockIdx.x * 64);
}

__global__ __launch_bounds__(256, 3) void qkv_gemm(
    const float* __restrict__ q, const float* __restrict__ k, const float* __restrict__ v,
    const float* __restrict__ Wq, const float* __restrict__ Wk, const float* __restrict__ Wv,
    const float* __restrict__ bq, const float* __restrict__ bk, const float* __restrict__ bv,
    float* __restrict__ oq, float* __restrict__ ok, float* __restrict__ ov) {
    const float *A, *W, *bias;
    float* C;
    if (blockIdx.z == 0)      { A = q; W = Wq; bias = bq; C = oq; }
    else if (blockIdx.z == 1) { A = k; W = Wk; bias = bk; C = ok; }
    else                      { A = v; W = Wv; bias = bv; C = ov; }
    gemm_body(A, W, bias, C, 4096, blockIdx.y * 128, blockIdx.x * 64);
}

// ---------------------------------------------------------------------------
// Fused rel-pos flash attention (R13: cK/cE precomputed in gmem; Ps stride 68
// with vectorized P@V; dead smem removed).
//
// Smem layout (floats):
//   qT  [64][68] @ 0       k-major raw q
//   ksT [64][68] @ 4352    k-major k tile
//   esT [64][68] @ 8704    k-major E rows (64 new)  -- Ps[64][68] aliases EXACTLY
//   vs  [64][64] @ 13056   row-major v tile
//   Rs  [64][128]@ 17152   q.E + cE ring
// total 25344 floats = 101376 B -> 2 CTAs/SM
// ---------------------------------------------------------------------------
#define ATT_SMEM_FLOATS 25344

__global__ __launch_bounds__(256, 2) void attn_kernel(
    const float* __restrict__ q, const float* __restrict__ k,
    const float* __restrict__ v, const float* __restrict__ E,
    const float* __restrict__ gcK, const float* __restrict__ gcE,
    float* __restrict__ out) {
    extern __shared__ float sm[];
    float* qT  = sm;            // [64][68]
    float* ksT = sm + 4352;     // [64][68]
    float* esT = sm + 8704;     // [64][68]
    float* Ps  = esT;           // [64][68] alias (lifetimes disjoint via syncs)
    float* vs  = sm + 13056;    // [64][64]
    float* Rs  = sm + 17152;    // [64][128]

    const int b = blockIdx.z, h = blockIdx.y;
    const int i0 = blockIdx.x * 64;
    const int t = threadIdx.x;
    const int tx = t & 15, ty = t >> 4;
    const int hoff = h * DHH;

    const float* qbase = q + (size_t)(b * TT + i0) * DD + hoff;
    const float* kbase = k + (size_t)b * TT * DD + hoff;
    const float* vbase = v + (size_t)b * TT * DD + hoff;
    const float* Ebase = E + hoff;
    const float* cKbase = gcK + ((b * HH + h) << 10);
    const float* cEbase = gcE + (h << 11);

    // ---- prologue: stage qT (transposed), first 63 E columns ----
    #pragma unroll
    for (int p = 0; p < 4; p++) {
        int g = p * 256 + t;
        int r = g >> 4, dq = g & 15;
        float4 val = *(const float4*)(qbase + (size_t)r * 512 + dq * 4);
        qT[(dq * 4 + 0) * 68 + r] = val.x;
        qT[(dq * 4 + 1) * 68 + r] = val.y;
        qT[(dq * 4 + 2) * 68 + r] = val.z;
        qT[(dq * 4 + 3) * 68 + r] = val.w;
    }

    const int rbase0 = 960 - i0;   // first window start (>= 0)
    #pragma unroll
    for (int p = 0; p < 4; p++) {
        int g = p * 256 + t;
        int c = g >> 4, dq = g & 15;
        float4 val = make_float4(0.f, 0.f, 0.f, 0.f);
        if (c < 63) val = *(const float4*)(Ebase + (size_t)(rbase0 + c) * 512 + dq * 4);
        esT[(dq * 4 + 0) * 68 + c] = val.x;
        esT[(dq * 4 + 1) * 68 + c] = val.y;
        esT[(dq * 4 + 2) * 68 + c] = val.z;
        esT[(dq * 4 + 3) * 68 + c] = val.w;
    }
    __syncthreads();

    // prologue: Rs for cols 0..62 (col 63 dummy; overwritten at kb=0)
    {
        float accR[4][4] = {};
        #pragma unroll 4
        for (int d = 0; d < 64; d++) {
            float4 a4 = *(const float4*)&qT[d * 68 + ty * 4];
            float4 e4 = *(const float4*)&esT[d * 68 + tx * 4];
            float a[4] = {a4.x, a4.y, a4.z, a4.w};
            float e[4] = {e4.x, e4.y, e4.z, e4.w};
            #pragma unroll
            for (int ii = 0; ii < 4; ii++)
                #pragma unroll
                for (int jj = 0; jj < 4; jj++)
                    accR[ii][jj] = fmaf(a[ii], e[jj], accR[ii][jj]);
        }
        float cE4[4];
        int slot[4];
        #pragma unroll
        for (int jj = 0; jj < 4; jj++) {
            int r = rbase0 + tx * 4 + jj;       // <= 960+63 = 1023, in range
            cE4[jj] = __ldg(cEbase + r);
            slot[jj] = r & 127;
        }
        #pragma unroll
        for (int ii = 0; ii < 4; ii++)
            #pragma unroll
            for (int jj = 0; jj < 4; jj++)
                Rs[(ty * 4 + ii) * 128 + slot[jj]] = accR[ii][jj] + cE4[jj];
    }

    float m_i[4], l_i[4], O[4][4];
    #pragma unroll
    for (int ii = 0; ii < 4; ii++) {
        m_i[ii] = -1e30f;
        l_i[ii] = 0.f;
        #pragma unroll
        for (int dd = 0; dd < 4; dd++) O[ii][dd] = 0.f;
    }

    // ---- main loop over key tiles ----
    for (int kb = 0; kb < 16; kb++) {
        const int j0 = kb * 64;
        const int rnb = j0 - i0 + 1023;   // base of the 64 NEW r columns, in [63,1983]

        __syncthreads();  // prev-iter consumers of ks/vs/es/Ps done

        // stage ksT (transposed), vs (row-major), esT (64 new E rows)
        #pragma unroll
        for (int p = 0; p < 4; p++) {
            int g = p * 256 + t;
            int r = g >> 4, dq = g & 15;
            float4 kv4 = *(const float4*)(kbase + (size_t)(j0 + r) * 512 + dq * 4);
            ksT[(dq * 4 + 0) * 68 + r] = kv4.x;
            ksT[(dq * 4 + 1) * 68 + r] = kv4.y;
            ksT[(dq * 4 + 2) * 68 + r] = kv4.z;
            ksT[(dq * 4 + 3) * 68 + r] = kv4.w;
            float4 vv4 = *(const float4*)(vbase + (size_t)(j0 + r) * 512 + dq * 4);
            *(float4*)(vs + r * 64 + dq * 4) = vv4;
            float4 ee4 = *(const float4*)(Ebase + (size_t)(rnb + r) * 512 + dq * 4);
            esT[(dq * 4 + 0) * 68 + r] = ee4.x;
            esT[(dq * 4 + 1) * 68 + r] = ee4.y;
            esT[(dq * 4 + 2) * 68 + r] = ee4.z;
            esT[(dq * 4 + 3) * 68 + r] = ee4.w;
        }
        __syncthreads();  // staging visible

        // fused R+S GEMM: 3x LDS.128 + 32 FFMA per d
        float accS[4][4] = {}, accR[4][4] = {};
        #pragma unroll 4
        for (int d = 0; d < 64; d++) {
            float4 a4 = *(const float4*)&qT[d * 68 + ty * 4];
            float4 k4 = *(const float4*)&ksT[d * 68 + tx * 4];
            float4 e4 = *(const float4*)&esT[d * 68 + tx * 4];
            float a[4] = {a4.x, a4.y, a4.z, a4.w};
            float kf[4] = {k4.x, k4.y, k4.z, k4.w};
            float ef[4] = {e4.x, e4.y, e4.z, e4.w};
            #pragma unroll
            for (int ii = 0; ii < 4; ii++) {
                #pragma unroll
                for (int jj = 0; jj < 4; jj++) {
                    accS[ii][jj] = fmaf(a[ii], kf[jj], accS[ii][jj]);
                    accR[ii][jj] = fmaf(a[ii], ef[jj], accR[ii][jj]);
                }
            }
        }
        // ring store with precomputed cE
        {
            float cE4[4];
            int slot[4];
            #pragma unroll
            for (int jj = 0; jj < 4; jj++) {
                int r = rnb + tx * 4 + jj;   // <= 1983+63 = 2046, in range
                cE4[jj] = __ldg(cEbase + r);
                slot[jj] = r & 127;
            }
            #pragma unroll
            for (int ii = 0; ii < 4; ii++)
                #pragma unroll
                for (int jj = 0; jj < 4; jj++)
                    Rs[(ty * 4 + ii) * 128 + slot[jj]] = accR[ii][jj] + cE4[jj];
        }
        __syncthreads();  // Rs visible; esT reads done (Ps alias writable)

        // softmax (online) — row group = 16 lanes sharing ty
        float4 cK4 = *(const float4*)(cKbase + j0 + tx * 4);
        float cK4v[4] = {cK4.x, cK4.y, cK4.z, cK4.w};
        #pragma unroll
        for (int ii = 0; ii < 4; ii++) {
            const int il = ty * 4 + ii;
            float Srow[4];
            float mloc = -1e30f;
            #pragma unroll
            for (int jj = 0; jj < 4; jj++) {
                float rterm = Rs[il * 128 + ((rnb - il + tx * 4 + jj) & 127)];
                float s = (accS[ii][jj] + cK4v[jj] + rterm) * 0.125f;
                Srow[jj] = s;
                mloc = fmaxf(mloc, s);
            }
            #pragma unroll
            for (int off = 8; off >= 1; off >>= 1)
                mloc = fmaxf(mloc, __shfl_xor_sync(0xffffffffu, mloc, off));
            const float mnew = fmaxf(m_i[ii], mloc);
            const float alpha = __expf(m_i[ii] - mnew);
            float psum = 0.f;
            float4 prow;
            prow.x = __expf(Srow[0] - mnew);
            prow.y = __expf(Srow[1] - mnew);
            prow.z = __expf(Srow[2] - mnew);
            prow.w = __expf(Srow[3] - mnew);
            psum = prow.x + prow.y + prow.z + prow.w;
            #pragma unroll
            for (int off = 8; off >= 1; off >>= 1)
                psum += __shfl_xor_sync(0xffffffffu, psum, off);
            l_i[ii] = l_i[ii] * alpha + psum;
            m_i[ii] = mnew;
            #pragma unroll
            for (int dd = 0; dd < 4; dd++) O[ii][dd] *= alpha;
            *(float4*)&Ps[il * 68 + tx * 4] = prow;   // one STS.128
        }
        __syncthreads();  // Ps visible

        // O += P @ V  (vectorized: per 4-j block, 4 broadcast LDS.128 of P + 4 vs rows)
        #pragma unroll 4
        for (int j4 = 0; j4 < 16; j4++) {
            float4 p4[4];
            #pragma unroll
            for (int ii = 0; ii < 4; ii++)
                p4[ii] = *(const float4*)&Ps[(ty * 4 + ii) * 68 + j4 * 4];
            #pragma unroll
            for (int jj = 0; jj < 4; jj++) {
                float4 v4 = *(const float4*)&vs[(j4 * 4 + jj) * 64 + tx * 4];
                float vf[4] = {v4.x, v4.y, v4.z, v4.w};
                float pv[4] = {
                    jj == 0 ? p4[0].x : jj == 1 ? p4[0].y : jj == 2 ? p4[0].z : p4[0].w,
                    jj == 0 ? p4[1].x : jj == 1 ? p4[1].y : jj == 2 ? p4[1].z : p4[1].w,
                    jj == 0 ? p4[2].x : jj == 1 ? p4[2].y : jj == 2 ? p4[2].z : p4[2].w,
                    jj == 0 ? p4[3].x : jj == 1 ? p4[3].y : jj == 2 ? p4[3].z : p4[3].w};
                #pragma unroll
                for (int ii = 0; ii < 4; ii++)
                    #pragma unroll
                    for (int dd = 0; dd < 4; dd++)
                        O[ii][dd] = fmaf(pv[ii], vf[dd], O[ii][dd]);
            }
        }
    }

    // epilogue
    #pragma unroll
    for (int ii = 0; ii < 4; ii++) {
        const int i = i0 + ty * 4 + ii;
        const float inv = 1.f / l_i[ii];
        float4 o;
        o.x = O[ii][0] * inv;
        o.y = O[ii][1] * inv;
        o.z = O[ii][2] * inv;
        o.w = O[ii][3] * inv;
        *(float4*)(out + (size_t)(b * TT + i) * DD + hoff + tx * 4) = o;
    }
}

// ---------------------------------------------------------------------------
extern "C" void kernel_launch(void* const* d_in, const int* in_sizes, int n_in,
                              void* d_out, int out_size) {
    const float* query  = (const float*)d_in[0];
    const float* key    = (const float*)d_in[1];
    const float* value  = (const float*)d_in[2];
    const float* Wq     = (const float*)d_in[3];
    const float* bq     = (const float*)d_in[4];
    const float* Wk     = (const float*)d_in[5];
    const float* bk     = (const float*)d_in[6];
    const float* Wv     = (const float*)d_in[7];
    const float* bv     = (const float*)d_in[8];
    const float* Wp     = (const float*)d_in[9];
    const float* bp     = (const float*)d_in[10];
    const float* Wo     = (const float*)d_in[11];
    const float* bo     = (const float*)d_in[12];
    const float* u_bias = (const float*)d_in[13];
    const float* v_bias = (const float*)d_in[14];
    float* out = (float*)d_out;

    float *pq, *pk, *pv, *ppe, *pE, *patt, *pcK, *pcE;
    cudaGetSymbolAddress((void**)&pq,  g_q);
    cudaGetSymbolAddress((void**)&pk,  g_k);
    cudaGetSymbolAddress((void**)&pv,  g_v);
    cudaGetSymbolAddress((void**)&ppe, g_pe);
    cudaGetSymbolAddress((void**)&pE,  g_E);
    cudaGetSymbolAddress((void**)&patt, g_att);
    cudaGetSymbolAddress((void**)&pcK, g_cK);
    cudaGetSymbolAddress((void**)&pcE, g_cE);

    // 1) positional encodings
    pe_kernel<<<(R2 * DD + 255) / 256, 256>>>(ppe);

    // 2) fused QKV projections + E projection
    qkv_gemm<<<dim3(8, 32, 3), 256>>>(query, key, value, Wq, Wk, Wv,
                                      bq, bk, bv, pq, pk, pv);
    gemm_nt<<<dim3(8, 16), 256>>>(ppe, Wp, bp, pE, 2047);

    // 2b) rank-1 bias precomputes (depend on pk and pE via stream order)
    ck_kernel<<<(BB * HH * TT + 255) / 256, 256>>>(pk, u_bias, pcK);
    ce_kernel<<<(HH * 2048 + 255) / 256, 256>>>(pE, v_bias, pcE);

    // 3) fused rel-pos flash attention
    cudaFuncSetAttribute(attn_kernel, cudaFuncAttributeMaxDynamicSharedMemorySize,
                         ATT_SMEM_FLOATS * (int)sizeof(float));
    attn_kernel<<<dim3(16, 8, 4), 256, ATT_SMEM_FLOATS * sizeof(float)>>>(
        pq, pk, pv, pE, pcK, pcE, patt);

    // 4) output projection -> d_out
    gemm_nt<<<dim3(8, 32), 256>>>(patt, Wo, bo, out, 4096);
}